// round 15
// baseline (speedup 1.0000x reference)
#include <cuda_runtime.h>
#include <cstdint>

// Problem constants
#define Bx 256
#define Tx 3000
#define Ix 40
#define Hx 64
#define Gx 256        // 4*H gates
#define RCH 8         // recurrent x_proj chunk steps (3000 % 8 == 0 -> 375 chunks)
#define XTK 50        // xproj tokens per block (3000 % 50 == 0)

// Scratch (allocation-free rule: __device__ globals)
__device__ float g_h[2][(size_t)Bx * Tx * Hx];    // per-direction hidden outputs
__device__ float g_xp[2][(size_t)Bx * Tx * Gx];   // input projections (+biases); dir1 time-reversed

// ---------- packed f32x2 helpers ----------
union F2U { float2 f; unsigned long long u; };

__device__ __forceinline__ void ffma2(unsigned long long& acc,
                                      unsigned long long a,
                                      unsigned long long b) {
    asm("fma.rn.f32x2 %0, %1, %2, %0;" : "+l"(acc) : "l"(a), "l"(b));
}
__device__ __forceinline__ unsigned long long fadd2(unsigned long long a, unsigned long long b) {
    unsigned long long r;
    asm("add.rn.f32x2 %0, %1, %2;" : "=l"(r) : "l"(a), "l"(b));
    return r;
}
__device__ __forceinline__ float fsigmoid(float x) {
    return __fdividef(1.0f, 1.0f + __expf(-x));
}
__device__ __forceinline__ float ftanh_fast(float x) {
    return 1.0f - __fdividef(2.0f, __expf(2.0f * x) + 1.0f);
}
__device__ __forceinline__ float hsum2(unsigned long long a, unsigned long long b) {
    F2U s; s.u = fadd2(a, b);
    return s.f.x + s.f.y;
}
__device__ __forceinline__ float hsum4(unsigned long long a, unsigned long long b,
                                       unsigned long long c, unsigned long long d) {
    F2U s; s.u = fadd2(fadd2(a, b), fadd2(c, d));
    return s.f.x + s.f.y;
}

// ---------- cp.async helpers ----------
__device__ __forceinline__ unsigned int smem_u32(const void* p) {
    return (unsigned int)__cvta_generic_to_shared(p);
}
__device__ __forceinline__ void cp_async16(unsigned int s, const void* g) {
    asm volatile("cp.async.cg.shared.global [%0], [%1], 16;" :: "r"(s), "l"(g));
}
#define CP_COMMIT() asm volatile("cp.async.commit_group;")
#define CP_WAIT1()  asm volatile("cp.async.wait_group 1;")

// ================= x-projection kernel (R5-exact, measured 822us) =================
__global__ __launch_bounds__(256, 2)
void xproj_kernel(const float* __restrict__ x,
                  const float* __restrict__ WihF, const float* __restrict__ bihF,
                  const float* __restrict__ bhhF,
                  const float* __restrict__ WihB, const float* __restrict__ bihB,
                  const float* __restrict__ bhhB)
{
    const int g = threadIdx.x;
    __shared__ __align__(16) float sx[XTK * Ix];   // 8 KB

    unsigned long long wf[20], wb[20];
    {
        const float2* wrf = (const float2*)(WihF + (size_t)g * Ix);
        const float2* wrb = (const float2*)(WihB + (size_t)g * Ix);
        #pragma unroll
        for (int j = 0; j < 20; j++) { F2U u; u.f = wrf[j]; wf[j] = u.u; }
        #pragma unroll
        for (int j = 0; j < 20; j++) { F2U u; u.f = wrb[j]; wb[j] = u.u; }
    }
    const float biasF = bihF[g] + bhhF[g];
    const float biasB = bihB[g] + bhhB[g];

    const int tiles_per_b = Tx / XTK;
    const int batch = blockIdx.x / tiles_per_b;
    const int trel  = (blockIdx.x % tiles_per_b) * XTK;

    {
        const float4* xs = (const float4*)(x + ((size_t)batch * Tx + trel) * Ix);
        float4* sd = (float4*)sx;
        #pragma unroll
        for (int i = 0; i < 2; i++) {
            int idx = threadIdx.x + i * 256;
            if (idx < XTK * Ix / 4) sd[idx] = xs[idx];
        }
    }
    __syncthreads();

    float* pF = g_xp[0] + ((size_t)batch * Tx + trel) * Gx + g;
    float* pB = g_xp[1] + ((size_t)batch * Tx + (Tx - 1 - trel)) * Gx + g;
    const ulonglong2* xr = (const ulonglong2*)sx;

    #pragma unroll 1
    for (int k = 0; k < XTK / 2; k++) {
        F2U fa0, fa1, ba0, ba1, fb0, fb1, bb0, bb1;
        fa0.f = make_float2(biasF, 0.0f); fa1.f = make_float2(0.0f, 0.0f);
        ba0.f = make_float2(biasB, 0.0f); ba1.f = make_float2(0.0f, 0.0f);
        fb0 = fa0; fb1 = fa1; bb0 = ba0; bb1 = ba1;
        #pragma unroll
        for (int j = 0; j < 10; j++) {
            const ulonglong2 ua = xr[j];            // token 2k
            const ulonglong2 ub = xr[10 + j];       // token 2k+1
            ffma2(fa0.u, ua.x, wf[2 * j]);  ffma2(fa1.u, ua.y, wf[2 * j + 1]);
            ffma2(ba0.u, ua.x, wb[2 * j]);  ffma2(ba1.u, ua.y, wb[2 * j + 1]);
            ffma2(fb0.u, ub.x, wf[2 * j]);  ffma2(fb1.u, ub.y, wf[2 * j + 1]);
            ffma2(bb0.u, ub.x, wb[2 * j]);  ffma2(bb1.u, ub.y, wb[2 * j + 1]);
        }
        xr += 20;
        pF[0]   = hsum2(fa0.u, fa1.u);
        pF[Gx]  = hsum2(fb0.u, fb1.u);
        pB[0]   = hsum2(ba0.u, ba1.u);
        pB[-Gx] = hsum2(bb0.u, bb1.u);
        pF += 2 * Gx;
        pB -= 2 * Gx;
    }
}

// ================= recurrent LSTM kernel (R13 + 4-chain phase-1) =================
__global__ __launch_bounds__(256, 2)
void lstm_kernel(const float* __restrict__ Whh_f, const float* __restrict__ Whh_b)
{
    const int dir   = blockIdx.x & 1;
    const int bpair = blockIdx.x >> 1;          // 0..127
    const int bA    = 2 * bpair;

    const float* Whh = dir ? Whh_b : Whh_f;
    float* hout = g_h[dir];
    const float* xpA = g_xp[dir] + (size_t)bA * Tx * Gx;
    const float* xpB = xpA + (size_t)Tx * Gx;

    const int g = threadIdx.x;

    __shared__ __align__(16) float sxp[2][2][RCH * Gx];  // [seq][buf] 32 KB
    __shared__ __align__(16) float sh[2][Hx];
    __shared__ float sgates[2][Gx];

    unsigned long long whh[32];
    {
        const float2* wr = (const float2*)(Whh + (size_t)g * Hx);
        #pragma unroll
        for (int j = 0; j < 32; j++) { F2U u; u.f = wr[j]; whh[j] = u.u; }
    }

    if (g < 128) sh[g >> 6][g & 63] = 0.0f;
    float c = 0.0f;
    const int region = g >> 6;
    const int us  = (g >> 6) & 1;
    const int uix = g & 63;

    {
        unsigned int sA = smem_u32(&sxp[0][0][0]) + threadIdx.x * 16;
        unsigned int sB = smem_u32(&sxp[1][0][0]) + threadIdx.x * 16;
        const char* gA = (const char*)xpA + threadIdx.x * 16;
        const char* gB = (const char*)xpB + threadIdx.x * 16;
        cp_async16(sA, gA); cp_async16(sA + 4096, gA + 4096);
        cp_async16(sB, gB); cp_async16(sB + 4096, gB + 4096);
        CP_COMMIT();
    }
    __syncthreads();

    const int NCH = Tx / RCH;
    for (int ck = 0; ck < NCH; ck++) {
        if (ck + 1 < NCH) {
            const int nb = (ck + 1) & 1;
            unsigned int sA = smem_u32(&sxp[0][nb][0]) + threadIdx.x * 16;
            unsigned int sB = smem_u32(&sxp[1][nb][0]) + threadIdx.x * 16;
            const char* gA = (const char*)(xpA + (size_t)(ck + 1) * RCH * Gx) + threadIdx.x * 16;
            const char* gB = (const char*)(xpB + (size_t)(ck + 1) * RCH * Gx) + threadIdx.x * 16;
            cp_async16(sA, gA); cp_async16(sA + 4096, gA + 4096);
            cp_async16(sB, gB); cp_async16(sB + 4096, gB + 4096);
        }
        CP_COMMIT();
        CP_WAIT1();
        __syncthreads();

        const int cb = ck & 1;
        const float* xbA = sxp[0][cb];
        const float* xbB = sxp[1][cb];

        for (int si = 0; si < RCH; si++) {
            const float xvA = xbA[si * Gx + g];
            const float xvB = xbB[si * Gx + g];

            // 4 chains per sequence (depth 8 instead of 16)
            F2U aA0, aA1, aA2, aA3, aB0, aB1, aB2, aB3;
            aA0.f = make_float2(xvA, 0.0f);
            aB0.f = make_float2(xvB, 0.0f);
            aA1.f = make_float2(0.0f, 0.0f);
            aA2 = aA1; aA3 = aA1;
            aB1 = aA1; aB2 = aA1; aB3 = aA1;

            const ulonglong2* hA = (const ulonglong2*)sh[0];
            const ulonglong2* hB = (const ulonglong2*)sh[1];
            #pragma unroll
            for (int j = 0; j < 8; j++) {
                const ulonglong2 ua  = hA[j];
                const ulonglong2 ua2 = hA[j + 8];
                const ulonglong2 ub  = hB[j];
                const ulonglong2 ub2 = hB[j + 8];
                ffma2(aA0.u, ua.x,  whh[2 * j]);
                ffma2(aA1.u, ua.y,  whh[2 * j + 1]);
                ffma2(aA2.u, ua2.x, whh[2 * j + 16]);
                ffma2(aA3.u, ua2.y, whh[2 * j + 17]);
                ffma2(aB0.u, ub.x,  whh[2 * j]);
                ffma2(aB1.u, ub.y,  whh[2 * j + 1]);
                ffma2(aB2.u, ub2.x, whh[2 * j + 16]);
                ffma2(aB3.u, ub2.y, whh[2 * j + 17]);
            }
            const float vA = hsum4(aA0.u, aA1.u, aA2.u, aA3.u);
            const float vB = hsum4(aB0.u, aB1.u, aB2.u, aB3.u);

            if (region == 2) {
                sgates[0][g] = ftanh_fast(vA);
                sgates[1][g] = ftanh_fast(vB);
            } else {
                sgates[0][g] = fsigmoid(vA);
                sgates[1][g] = fsigmoid(vB);
            }
            __syncthreads();

            if (g < 128) {
                const float ig = sgates[us][uix];
                const float fg = sgates[us][64 + uix];
                const float gg = sgates[us][128 + uix];
                const float og = sgates[us][192 + uix];
                c = fg * c + ig * gg;
                const float h = og * ftanh_fast(c);
                sh[us][uix] = h;
                const int srel = ck * RCH + si;
                const int t = dir ? (Tx - 1 - srel) : srel;
                hout[((size_t)(bA + us) * Tx + t) * Hx + uix] = h;
            }
            __syncthreads();
        }
    }
}

// ================= MLP head kernel (R1 shape + 2x o-unroll, 8 chains) =================
// one thread per token. FIX vs R14: inner loop covers ALL 32 ulonglong2 tiles
// of the 128-float W1 row / h vector (was 16 -> dropped the hb half).
__global__ __launch_bounds__(256, 1)
void head_kernel(const float* __restrict__ W1, const float* __restrict__ b1,
                 const float* __restrict__ W2, const float* __restrict__ b2,
                 float* __restrict__ out)
{
    __shared__ __align__(16) float sW1[64 * 128];  // 32 KB
    __shared__ float sb1[64];
    __shared__ float sW2[64];
    __shared__ float sb2;

    const int tid = threadIdx.x;
    for (int i = tid; i < 64 * 128 / 4; i += 256)
        ((float4*)sW1)[i] = ((const float4*)W1)[i];
    if (tid < 64) { sb1[tid] = b1[tid]; sW2[tid] = W2[tid]; }
    if (tid == 0) sb2 = b2[0];
    __syncthreads();

    const size_t tok = (size_t)blockIdx.x * 256 + tid;

    unsigned long long hreg[64];
    {
        const float2* pf = (const float2*)(g_h[0] + tok * Hx);
        const float2* pb = (const float2*)(g_h[1] + tok * Hx);
        #pragma unroll
        for (int j = 0; j < 32; j++) { F2U u; u.f = pf[j]; hreg[j] = u.u; }
        #pragma unroll
        for (int j = 0; j < 32; j++) { F2U u; u.f = pb[j]; hreg[32 + j] = u.u; }
    }

    float acc_out = sb2;
    #pragma unroll 1
    for (int o = 0; o < 64; o += 2) {
        F2U a0, a1, a2, a3, c0, c1, c2, c3;
        a0.f = make_float2(sb1[o], 0.0f);
        a1.f = make_float2(0.0f, 0.0f);
        a2 = a1; a3 = a1;
        c0.f = make_float2(sb1[o + 1], 0.0f);
        c1 = a1; c2 = a1; c3 = a1;

        const ulonglong2* w0 = (const ulonglong2*)(sW1 + o * 128);        // 32 tiles
        const ulonglong2* w1 = (const ulonglong2*)(sW1 + (o + 1) * 128);
        #pragma unroll
        for (int j = 0; j < 32; j++) {   // FULL 128-float row (fix)
            const ulonglong2 wa = w0[j];
            const ulonglong2 wb = w1[j];
            const unsigned long long h0 = hreg[2 * j];
            const unsigned long long h1 = hreg[2 * j + 1];
            if (j & 1) {
                ffma2(a2.u, h0, wa.x);  ffma2(a3.u, h1, wa.y);
                ffma2(c2.u, h0, wb.x);  ffma2(c3.u, h1, wb.y);
            } else {
                ffma2(a0.u, h0, wa.x);  ffma2(a1.u, h1, wa.y);
                ffma2(c0.u, h0, wb.x);  ffma2(c1.u, h1, wb.y);
            }
        }
        const float z0 = fmaxf(hsum4(a0.u, a1.u, a2.u, a3.u), 0.0f);
        const float z1 = fmaxf(hsum4(c0.u, c1.u, c2.u, c3.u), 0.0f);
        acc_out = fmaf(z0, sW2[o], acc_out);
        acc_out = fmaf(z1, sW2[o + 1], acc_out);
    }
    out[tok] = fsigmoid(acc_out);
}

// ================= launch =================
extern "C" void kernel_launch(void* const* d_in, const int* in_sizes, int n_in,
                              void* d_out, int out_size)
{
    const float* x     = (const float*)d_in[0];
    const float* Wih_f = (const float*)d_in[1];
    const float* Whh_f = (const float*)d_in[2];
    const float* bih_f = (const float*)d_in[3];
    const float* bhh_f = (const float*)d_in[4];
    const float* Wih_b = (const float*)d_in[5];
    const float* Whh_b = (const float*)d_in[6];
    const float* bih_b = (const float*)d_in[7];
    const float* bhh_b = (const float*)d_in[8];
    const float* W1    = (const float*)d_in[9];
    const float* b1    = (const float*)d_in[10];
    const float* W2    = (const float*)d_in[11];
    const float* b2    = (const float*)d_in[12];
    float* out = (float*)d_out;

    xproj_kernel<<<Bx * (Tx / XTK), 256>>>(x, Wih_f, bih_f, bhh_f, Wih_b, bih_b, bhh_b);
    lstm_kernel<<<Bx, 256>>>(Whh_f, Whh_b);
    head_kernel<<<(Bx * Tx) / 256, 256>>>(W1, b1, W2, b2, out);
}

// round 16
// speedup vs baseline: 1.0052x; 1.0052x over previous
#include <cuda_runtime.h>
#include <cstdint>

// Problem constants
#define Bx 256
#define Tx 3000
#define Ix 40
#define Hx 64
#define Gx 256        // 4*H gates
#define RCH 8         // recurrent x_proj chunk steps (3000 % 8 == 0 -> 375 chunks)
#define XTK 50        // xproj tokens per block (3000 % 50 == 0)
#define HTK 160       // head tokens per block (768000 % 160 == 0 -> 4800 blocks)

// Scratch (allocation-free rule: __device__ globals)
__device__ float g_h[2][(size_t)Bx * Tx * Hx];    // per-direction hidden outputs
__device__ float g_xp[2][(size_t)Bx * Tx * Gx];   // input projections (+biases); dir1 time-reversed

// ---------- packed f32x2 helpers ----------
union F2U { float2 f; unsigned long long u; };

__device__ __forceinline__ void ffma2(unsigned long long& acc,
                                      unsigned long long a,
                                      unsigned long long b) {
    asm("fma.rn.f32x2 %0, %1, %2, %0;" : "+l"(acc) : "l"(a), "l"(b));
}
__device__ __forceinline__ unsigned long long fadd2(unsigned long long a, unsigned long long b) {
    unsigned long long r;
    asm("add.rn.f32x2 %0, %1, %2;" : "=l"(r) : "l"(a), "l"(b));
    return r;
}
__device__ __forceinline__ float fsigmoid(float x) {
    return __fdividef(1.0f, 1.0f + __expf(-x));
}
__device__ __forceinline__ float ftanh_fast(float x) {
    return 1.0f - __fdividef(2.0f, __expf(2.0f * x) + 1.0f);
}
__device__ __forceinline__ float hsum2(unsigned long long a, unsigned long long b) {
    F2U s; s.u = fadd2(a, b);
    return s.f.x + s.f.y;
}

// ---------- cp.async helpers ----------
__device__ __forceinline__ unsigned int smem_u32(const void* p) {
    return (unsigned int)__cvta_generic_to_shared(p);
}
__device__ __forceinline__ void cp_async16(unsigned int s, const void* g) {
    asm volatile("cp.async.cg.shared.global [%0], [%1], 16;" :: "r"(s), "l"(g));
}
#define CP_COMMIT() asm volatile("cp.async.commit_group;")
#define CP_WAIT1()  asm volatile("cp.async.wait_group 1;")

// ================= x-projection kernel (R5/R13-exact, measured 822us) =================
__global__ __launch_bounds__(256, 2)
void xproj_kernel(const float* __restrict__ x,
                  const float* __restrict__ WihF, const float* __restrict__ bihF,
                  const float* __restrict__ bhhF,
                  const float* __restrict__ WihB, const float* __restrict__ bihB,
                  const float* __restrict__ bhhB)
{
    const int g = threadIdx.x;
    __shared__ __align__(16) float sx[XTK * Ix];   // 8 KB

    unsigned long long wf[20], wb[20];
    {
        const float2* wrf = (const float2*)(WihF + (size_t)g * Ix);
        const float2* wrb = (const float2*)(WihB + (size_t)g * Ix);
        #pragma unroll
        for (int j = 0; j < 20; j++) { F2U u; u.f = wrf[j]; wf[j] = u.u; }
        #pragma unroll
        for (int j = 0; j < 20; j++) { F2U u; u.f = wrb[j]; wb[j] = u.u; }
    }
    const float biasF = bihF[g] + bhhF[g];
    const float biasB = bihB[g] + bhhB[g];

    const int tiles_per_b = Tx / XTK;
    const int batch = blockIdx.x / tiles_per_b;
    const int trel  = (blockIdx.x % tiles_per_b) * XTK;

    {
        const float4* xs = (const float4*)(x + ((size_t)batch * Tx + trel) * Ix);
        float4* sd = (float4*)sx;
        #pragma unroll
        for (int i = 0; i < 2; i++) {
            int idx = threadIdx.x + i * 256;
            if (idx < XTK * Ix / 4) sd[idx] = xs[idx];
        }
    }
    __syncthreads();

    float* pF = g_xp[0] + ((size_t)batch * Tx + trel) * Gx + g;
    float* pB = g_xp[1] + ((size_t)batch * Tx + (Tx - 1 - trel)) * Gx + g;
    const ulonglong2* xr = (const ulonglong2*)sx;

    #pragma unroll 1
    for (int k = 0; k < XTK / 2; k++) {
        F2U fa0, fa1, ba0, ba1, fb0, fb1, bb0, bb1;
        fa0.f = make_float2(biasF, 0.0f); fa1.f = make_float2(0.0f, 0.0f);
        ba0.f = make_float2(biasB, 0.0f); ba1.f = make_float2(0.0f, 0.0f);
        fb0 = fa0; fb1 = fa1; bb0 = ba0; bb1 = ba1;
        #pragma unroll
        for (int j = 0; j < 10; j++) {
            const ulonglong2 ua = xr[j];            // token 2k
            const ulonglong2 ub = xr[10 + j];       // token 2k+1
            ffma2(fa0.u, ua.x, wf[2 * j]);  ffma2(fa1.u, ua.y, wf[2 * j + 1]);
            ffma2(ba0.u, ua.x, wb[2 * j]);  ffma2(ba1.u, ua.y, wb[2 * j + 1]);
            ffma2(fb0.u, ub.x, wf[2 * j]);  ffma2(fb1.u, ub.y, wf[2 * j + 1]);
            ffma2(bb0.u, ub.x, wb[2 * j]);  ffma2(bb1.u, ub.y, wb[2 * j + 1]);
        }
        xr += 20;
        pF[0]   = hsum2(fa0.u, fa1.u);
        pF[Gx]  = hsum2(fb0.u, fb1.u);
        pB[0]   = hsum2(ba0.u, ba1.u);
        pB[-Gx] = hsum2(bb0.u, bb1.u);
        pF += 2 * Gx;
        pB -= 2 * Gx;
    }
}

// ================= recurrent LSTM kernel (R13-exact: R3 + phase-2 guard) =================
__global__ __launch_bounds__(256, 2)
void lstm_kernel(const float* __restrict__ Whh_f, const float* __restrict__ Whh_b)
{
    const int dir   = blockIdx.x & 1;
    const int bpair = blockIdx.x >> 1;          // 0..127
    const int bA    = 2 * bpair;

    const float* Whh = dir ? Whh_b : Whh_f;
    float* hout = g_h[dir];
    const float* xpA = g_xp[dir] + (size_t)bA * Tx * Gx;
    const float* xpB = xpA + (size_t)Tx * Gx;

    const int g = threadIdx.x;

    __shared__ __align__(16) float sxp[2][2][RCH * Gx];  // [seq][buf] 32 KB
    __shared__ __align__(16) float sh[2][Hx];
    __shared__ float sgates[2][Gx];

    unsigned long long whh[32];
    {
        const float2* wr = (const float2*)(Whh + (size_t)g * Hx);
        #pragma unroll
        for (int j = 0; j < 32; j++) { F2U u; u.f = wr[j]; whh[j] = u.u; }
    }

    if (g < 128) sh[g >> 6][g & 63] = 0.0f;
    float c = 0.0f;
    const int region = g >> 6;
    const int us  = (g >> 6) & 1;
    const int uix = g & 63;

    {
        unsigned int sA = smem_u32(&sxp[0][0][0]) + threadIdx.x * 16;
        unsigned int sB = smem_u32(&sxp[1][0][0]) + threadIdx.x * 16;
        const char* gA = (const char*)xpA + threadIdx.x * 16;
        const char* gB = (const char*)xpB + threadIdx.x * 16;
        cp_async16(sA, gA); cp_async16(sA + 4096, gA + 4096);
        cp_async16(sB, gB); cp_async16(sB + 4096, gB + 4096);
        CP_COMMIT();
    }
    __syncthreads();

    const int NCH = Tx / RCH;
    for (int ck = 0; ck < NCH; ck++) {
        if (ck + 1 < NCH) {
            const int nb = (ck + 1) & 1;
            unsigned int sA = smem_u32(&sxp[0][nb][0]) + threadIdx.x * 16;
            unsigned int sB = smem_u32(&sxp[1][nb][0]) + threadIdx.x * 16;
            const char* gA = (const char*)(xpA + (size_t)(ck + 1) * RCH * Gx) + threadIdx.x * 16;
            const char* gB = (const char*)(xpB + (size_t)(ck + 1) * RCH * Gx) + threadIdx.x * 16;
            cp_async16(sA, gA); cp_async16(sA + 4096, gA + 4096);
            cp_async16(sB, gB); cp_async16(sB + 4096, gB + 4096);
        }
        CP_COMMIT();
        CP_WAIT1();
        __syncthreads();

        const int cb = ck & 1;
        const float* xbA = sxp[0][cb];
        const float* xbB = sxp[1][cb];

        for (int si = 0; si < RCH; si++) {
            const float xvA = xbA[si * Gx + g];
            const float xvB = xbB[si * Gx + g];

            F2U aA0, aA1, aB0, aB1;
            aA0.f = make_float2(xvA, 0.0f);
            aB0.f = make_float2(xvB, 0.0f);
            aA1.f = make_float2(0.0f, 0.0f);
            aB1 = aA1;

            const ulonglong2* hA = (const ulonglong2*)sh[0];  // LDS.128 broadcast
            const ulonglong2* hB = (const ulonglong2*)sh[1];
            #pragma unroll
            for (int j = 0; j < 16; j++) {
                const ulonglong2 ua = hA[j];
                const ulonglong2 ub = hB[j];
                ffma2(aA0.u, ua.x, whh[2 * j]);
                ffma2(aA1.u, ua.y, whh[2 * j + 1]);
                ffma2(aB0.u, ub.x, whh[2 * j]);
                ffma2(aB1.u, ub.y, whh[2 * j + 1]);
            }
            const float vA = hsum2(aA0.u, aA1.u);
            const float vB = hsum2(aB0.u, aB1.u);

            if (region == 2) {
                sgates[0][g] = ftanh_fast(vA);
                sgates[1][g] = ftanh_fast(vB);
            } else {
                sgates[0][g] = fsigmoid(vA);
                sgates[1][g] = fsigmoid(vB);
            }
            __syncthreads();

            if (g < 128) {
                const float ig = sgates[us][uix];
                const float fg = sgates[us][64 + uix];
                const float gg = sgates[us][128 + uix];
                const float og = sgates[us][192 + uix];
                c = fg * c + ig * gg;
                const float h = og * ftanh_fast(c);
                sh[us][uix] = h;
                const int srel = ck * RCH + si;
                const int t = dir ? (Tx - 1 - srel) : srel;
                hout[((size_t)(bA + us) * Tx + t) * Hx + uix] = h;
            }
            __syncthreads();
        }
    }
}

// ================= MLP head kernel (R1 body, geometry 160thr x 2 blocks/SM) =================
// one thread per token; W1 broadcast from SMEM; h in registers; 4 f32x2 chains.
// 160 threads + launch_bounds(160,2): reg budget 204 >= 202 measured -> no spill,
// 10 warps/SM (vs 8) for better latency hiding.
__global__ __launch_bounds__(HTK, 2)
void head_kernel(const float* __restrict__ W1, const float* __restrict__ b1,
                 const float* __restrict__ W2, const float* __restrict__ b2,
                 float* __restrict__ out)
{
    __shared__ __align__(16) float sW1[64 * 128];  // 32 KB
    __shared__ float sb1[64];
    __shared__ float sW2[64];
    __shared__ float sb2;

    const int tid = threadIdx.x;
    for (int i = tid; i < 64 * 128 / 4; i += HTK)
        ((float4*)sW1)[i] = ((const float4*)W1)[i];
    if (tid < 64) { sb1[tid] = b1[tid]; sW2[tid] = W2[tid]; }
    if (tid == 0) sb2 = b2[0];
    __syncthreads();

    const size_t tok = (size_t)blockIdx.x * HTK + tid;

    // load h = [hf(64) ; hb(64)] into registers as 64 packed f32x2
    unsigned long long hreg[64];
    {
        const float2* pf = (const float2*)(g_h[0] + tok * Hx);
        const float2* pb = (const float2*)(g_h[1] + tok * Hx);
        #pragma unroll
        for (int j = 0; j < 32; j++) { F2U u; u.f = pf[j]; hreg[j] = u.u; }
        #pragma unroll
        for (int j = 0; j < 32; j++) { F2U u; u.f = pb[j]; hreg[32 + j] = u.u; }
    }

    float acc_out = sb2;
    for (int o = 0; o < 64; o++) {
        F2U a0, a1, a2, a3;
        a0.f = make_float2(sb1[o], 0.0f);
        a1.f = make_float2(0.0f, 0.0f);
        a2.f = a1.f; a3.f = a1.f;
        const ulonglong2* w = (const ulonglong2*)(sW1 + o * 128);  // 16B LDS, broadcast
        #pragma unroll
        for (int j = 0; j < 16; j++) {
            const ulonglong2 wv0 = w[2 * j];
            const ulonglong2 wv1 = w[2 * j + 1];
            ffma2(a0.u, hreg[4 * j + 0], wv0.x);
            ffma2(a1.u, hreg[4 * j + 1], wv0.y);
            ffma2(a2.u, hreg[4 * j + 2], wv1.x);
            ffma2(a3.u, hreg[4 * j + 3], wv1.y);
        }
        float z = (a0.f.x + a0.f.y) + (a1.f.x + a1.f.y)
                + (a2.f.x + a2.f.y) + (a3.f.x + a3.f.y);
        z = fmaxf(z, 0.0f);
        acc_out = fmaf(z, sW2[o], acc_out);
    }
    out[tok] = fsigmoid(acc_out);
}

// ================= launch =================
extern "C" void kernel_launch(void* const* d_in, const int* in_sizes, int n_in,
                              void* d_out, int out_size)
{
    const float* x     = (const float*)d_in[0];
    const float* Wih_f = (const float*)d_in[1];
    const float* Whh_f = (const float*)d_in[2];
    const float* bih_f = (const float*)d_in[3];
    const float* bhh_f = (const float*)d_in[4];
    const float* Wih_b = (const float*)d_in[5];
    const float* Whh_b = (const float*)d_in[6];
    const float* bih_b = (const float*)d_in[7];
    const float* bhh_b = (const float*)d_in[8];
    const float* W1    = (const float*)d_in[9];
    const float* b1    = (const float*)d_in[10];
    const float* W2    = (const float*)d_in[11];
    const float* b2    = (const float*)d_in[12];
    float* out = (float*)d_out;

    xproj_kernel<<<Bx * (Tx / XTK), 256>>>(x, Wih_f, bih_f, bhh_f, Wih_b, bih_b, bhh_b);
    lstm_kernel<<<Bx, 256>>>(Whh_f, Whh_b);
    head_kernel<<<(Bx * Tx) / HTK, HTK>>>(W1, b1, W2, b2, out);
}